// round 10
// baseline (speedup 1.0000x reference)
#include <cuda_runtime.h>
#include <cuda_bf16.h>
#include <stdint.h>
#include <math.h>

#define Dm   512
#define Hh   8
#define DKk  64
#define Ff   2048
#define Ll   6
#define Bb   2
#define Ss   1024
#define NT   2048
#define Vv   32000
#define TM   128
typedef __nv_bfloat16 bf;

#if defined(__CUDA_ARCH__) && defined(__CUDA_ARCH_FEAT_SM103_ALL)
#define TC 1
#else
#define TC 0
#endif

// ---------------- bf16 pool offsets (elements) ----------------
#define WEAH 0LL
#define WEAL 6291456LL
#define WDSH 12582912LL
#define WDSL 18874368LL
#define WDCH 25165824LL
#define WDCL 31457280LL
#define WE1H 37748736LL
#define WE1L 44040192LL
#define WE2H 50331648LL
#define WE2L 56623104LL
#define WD1H 62914560LL
#define WD1L 69206016LL
#define WD2H 75497472LL
#define WD2L 81788928LL
#define EMBH 88080384LL
#define EMBL 104464384LL
#define NBH  120848384LL
#define NBL  121896960LL
#define ENH  122945536LL
#define ENL  123994112LL
#define FNH  125042688LL
#define FNL  129236992LL
#define QBH  133431296LL
#define QBL  134479872LL
#define KBH  135528448LL
#define KBL  136577024LL
#define CTH  137625600LL
#define CTL  138674176LL
#define VTH  139722752LL
#define VTL  140771328LL
#define PRH  141819904LL
#define PRL  158597120LL
#define BFTOT 175374336LL
// fp32 pool offsets
#define Xo   0LL
#define Yo   1048576LL
#define Qo   2097152LL
#define Ko   3145728LL
#define Vo   4194304LL
#define SCo  5242880LL
#define FTOT 22020096LL

__device__ __align__(256) bf    g_bf[BFTOT];
__device__ __align__(256) float g_f[FTOT];

// ---------------- helpers ----------------
__device__ __forceinline__ uint32_t smem_u32(const void* p) {
    uint32_t a;
    asm("{ .reg .u64 t; cvta.to.shared.u64 t, %1; cvt.u32.u64 %0, t; }" : "=r"(a) : "l"(p));
    return a;
}
__device__ __forceinline__ void split2(float v, bf* ph, bf* pl) {
    bf h = __float2bfloat16(v);
    *ph = h;
    *pl = __float2bfloat16(v - __bfloat162float(h));
}

#if TC
__device__ __forceinline__ uint32_t elect1() {
    uint32_t p;
    asm volatile("{ .reg .pred p; elect.sync _|p, 0xFFFFFFFF; selp.b32 %0,1,0,p; }" : "=r"(p));
    return p;
}
__device__ __forceinline__ uint64_t mk_desc(uint32_t a) {
    // SW128 K-major: layout=2, version=1, SBO=64, LBO=1
    return (uint64_t(2) << 61) | (uint64_t(1) << 46) | (uint64_t(64) << 32)
         | (uint64_t(1) << 16) | (uint64_t)((a >> 4) & 0x3FFF);
}
__device__ __forceinline__ void cpa16(uint32_t d, const void* s) {
    asm volatile("cp.async.cg.shared.global [%0], [%1], 16;" :: "r"(d), "l"(s));
}
__device__ __forceinline__ void cpa_commit() { asm volatile("cp.async.commit_group;" ::: "memory"); }
template<int N> __device__ __forceinline__ void cpa_wait() {
    asm volatile("cp.async.wait_group %0;" :: "n"(N) : "memory");
}
__device__ __forceinline__ void mma_f16_ss(uint32_t d, uint64_t da, uint64_t db,
                                           uint32_t idesc, uint32_t en) {
    asm volatile(
        "{\n\t.reg .pred p;\n\tsetp.ne.u32 p, %5, 0;\n\t"
        "tcgen05.mma.cta_group::1.kind::f16 [%0], %1, %2, %3, {%4, %4, %4, %4}, p;\n\t}"
        :: "r"(d), "l"(da), "l"(db), "r"(idesc), "r"(0u), "r"(en) : "memory");
}
#define TG_ALLOC(sm, n)   asm volatile("tcgen05.alloc.cta_group::1.sync.aligned.shared::cta.b32 [%0], %1;" :: "r"(sm), "r"(n) : "memory")
#define TG_DEALLOC(t, n)  asm volatile("tcgen05.dealloc.cta_group::1.sync.aligned.b32 %0, %1;" :: "r"(t), "r"(n))
#define TG_COMMIT(mb)     asm volatile("tcgen05.commit.cta_group::1.mbarrier::arrive::one.shared::cluster.b64 [%0];" :: "r"(mb) : "memory")
#define TG_FENCE_AFTER()  asm volatile("tcgen05.fence::after_thread_sync;" ::: "memory")
#define TG_WAIT_LD()      asm volatile("tcgen05.wait::ld.sync.aligned;" ::: "memory")
#define FENCE_PROXY()     asm volatile("fence.proxy.async.shared::cta;" ::: "memory")
#define MBAR_INIT(mb, c)  asm volatile("mbarrier.init.shared.b64 [%0], %1;" :: "r"(mb), "r"(c) : "memory")

__device__ __forceinline__ void mbar_wait(uint32_t mb, uint32_t parity) {
    asm volatile(
        "{\n\t.reg .pred P1;\n\t"
        "WL_%=:\n\t"
        "mbarrier.try_wait.parity.acquire.cta.shared::cta.b64 P1, [%0], %1, 0x989680;\n\t"
        "@P1 bra.uni WD_%=;\n\t"
        "bra.uni WL_%=;\n\t"
        "WD_%=:\n\t}"
        :: "r"(mb), "r"(parity) : "memory");
}
#define LDTM_X32(r, a) \
    asm volatile("tcgen05.ld.sync.aligned.32x32b.x32.b32 " \
        "{%0,%1,%2,%3,%4,%5,%6,%7,%8,%9,%10,%11,%12,%13,%14,%15," \
        "%16,%17,%18,%19,%20,%21,%22,%23,%24,%25,%26,%27,%28,%29,%30,%31}, [%32];" \
        : "=r"((r)[0]),"=r"((r)[1]),"=r"((r)[2]),"=r"((r)[3]),"=r"((r)[4]),"=r"((r)[5]),"=r"((r)[6]),"=r"((r)[7]), \
          "=r"((r)[8]),"=r"((r)[9]),"=r"((r)[10]),"=r"((r)[11]),"=r"((r)[12]),"=r"((r)[13]),"=r"((r)[14]),"=r"((r)[15]), \
          "=r"((r)[16]),"=r"((r)[17]),"=r"((r)[18]),"=r"((r)[19]),"=r"((r)[20]),"=r"((r)[21]),"=r"((r)[22]),"=r"((r)[23]), \
          "=r"((r)[24]),"=r"((r)[25]),"=r"((r)[26]),"=r"((r)[27]),"=r"((r)[28]),"=r"((r)[29]),"=r"((r)[30]),"=r"((r)[31]) \
        : "r"(a))
#endif  // TC

// ---------------- split-bf16 GEMM ----------------
// D[M,N] = (Ah+Al)[M,K] @ (Bh+Bl)[N,K]^T, fp32 accumulation.
// tcgen05 path on sm_103a; fp32-FMA fallback body on generic targets (correct, slow).
template<int TN, int NS, bool BIAS, bool RELU, bool ACC, bool OSPLIT, bool WRITEC>
__global__ void __launch_bounds__(256, 1) tg_k(
    const bf* __restrict__ Ah, const bf* __restrict__ Al,
    const bf* __restrict__ Bh, const bf* __restrict__ Bl,
    const float* __restrict__ bias, float* __restrict__ C,
    bf* __restrict__ Oh, bf* __restrict__ Ol,
    int Kd, int lda, int ldb, int ldc,
    long long sA1, long long sA2, long long sB1, long long sB2,
    long long sC1, long long sC2, int Hb)
{
    extern __shared__ char smraw[];
    int z = blockIdx.z, zb = z / Hb, zh = z - zb * Hb;
    const bf* ah = Ah + zb * sA1 + zh * sA2;
    const bf* al = Al + zb * sA1 + zh * sA2;
    const bf* bh = Bh + zb * sB1 + zh * sB2;
    const bf* bl = Bl + zb * sB1 + zh * sB2;
    const long long coff = zb * sC1 + zh * sC2;
    int m0 = blockIdx.y * TM, n0 = blockIdx.x * TN;
    int tid = threadIdx.x;

#if TC
    constexpr int SSZ = (2 * TM + 2 * TN) * 128;
    uint32_t smb = (smem_u32(smraw) + 1023u) & ~1023u;

    if (tid < NS) MBAR_INIT(smb + tid * 8, 1);
    if (tid < 32) TG_ALLOC(smb + 64, 128);
    __syncthreads();
    uint32_t tmem;
    asm("ld.shared.b32 %0,[%1];" : "=r"(tmem) : "r"(smb + 64));

    const uint32_t idesc = (1u << 4) | (1u << 7) | (1u << 10)
                         | ((uint32_t)(TN / 8) << 17) | ((uint32_t)(TM / 16) << 24);
    const int nk = Kd >> 6;

    auto fill = [&](int s, int kc) {
        uint32_t st = smb + 1024 + s * SSZ;
        int k0 = kc * 64;
        #pragma unroll
        for (int t = tid; t < TM * 8; t += 256) {
            int r = t >> 3, c = t & 7;
            uint32_t d = st + r * 128 + (uint32_t)((c * 16) ^ ((r & 7) << 4));
            long long off = (long long)(m0 + r) * lda + k0 + c * 8;
            cpa16(d, ah + off);
            cpa16(d + TM * 128, al + off);
        }
        #pragma unroll
        for (int t = tid; t < TN * 8; t += 256) {
            int r = t >> 3, c = t & 7;
            uint32_t d = st + 2 * TM * 128 + r * 128 + (uint32_t)((c * 16) ^ ((r & 7) << 4));
            long long off = (long long)(n0 + r) * ldb + k0 + c * 8;
            cpa16(d, bh + off);
            cpa16(d + TN * 128, bl + off);
        }
        cpa_commit();
    };

    int pre = (NS < nk) ? NS : nk;
    for (int i = 0; i < pre; i++) fill(i, i);
    for (int i = pre; i < NS; i++) cpa_commit();

    for (int i = 0; i < nk; i++) {
        int s = i % NS;
        cpa_wait<NS - 1>();
        __syncthreads();
        FENCE_PROXY();
        if (tid < 32 && elect1()) {
            uint32_t st = smb + 1024 + s * SSZ;
            uint64_t dah = mk_desc(st);
            uint64_t dal = mk_desc(st + TM * 128);
            uint64_t dbh = mk_desc(st + 2 * TM * 128);
            uint64_t dbl = mk_desc(st + 2 * TM * 128 + TN * 128);
            uint32_t en = (i > 0) ? 1u : 0u;
            #pragma unroll
            for (int j = 0; j < 4; j++) {
                mma_f16_ss(tmem, dah + j * 2, dbh + j * 2, idesc, en); en = 1u;
                mma_f16_ss(tmem, dah + j * 2, dbl + j * 2, idesc, 1u);
                mma_f16_ss(tmem, dal + j * 2, dbh + j * 2, idesc, 1u);
            }
            TG_COMMIT(smb + s * 8);
        }
        int pf = i + NS;
        if (pf < nk) {
            mbar_wait(smb + s * 8, (uint32_t)((i / NS) & 1));
            fill(s, pf);
        } else {
            cpa_commit();
        }
    }

    int sl = (nk - 1) % NS;
    mbar_wait(smb + sl * 8, (uint32_t)(((nk - 1) / NS) & 1));
    TG_FENCE_AFTER();

    int w = tid >> 5, lid = tid & 31;
    int sub = w & 3, half = w >> 2;
    int row = m0 + sub * 32 + lid;
    #pragma unroll
    for (int c0 = half * (TN / 2); c0 < (half + 1) * (TN / 2); c0 += 32) {
        uint32_t r[32];
        LDTM_X32(r, tmem + c0);
        TG_WAIT_LD();
        long long rb = (long long)row * ldc + n0 + c0 + coff;
        #pragma unroll
        for (int c = 0; c < 32; c++) {
            float v = __uint_as_float(r[c]);
            if (BIAS) v += bias[n0 + c0 + c];
            if (RELU) v = fmaxf(v, 0.f);
            if (ACC)  v += C[rb + c];
            if (WRITEC) C[rb + c] = v;
            if (OSPLIT) split2(v, Oh + rb + c, Ol + rb + c);
        }
    }
    __syncthreads();
    if (tid < 32) TG_DEALLOC(tmem, 128);
#else
    // -------- generic fallback: smem-tiled fp32 FMA, correct on any target --------
    float* As = (float*)smraw;          // [16][TM]
    float* Bs = As + 16 * TM;           // [16][TN]
    int ty = tid >> 4, tx = tid & 15;
    constexpr int RM = TM / 16, RN = TN / 16;
    float acc[RM][RN] = {};
    for (int k0 = 0; k0 < Kd; k0 += 16) {
        __syncthreads();
        for (int t = tid; t < TM * 16; t += 256) {
            int r = t >> 4, kk = t & 15;
            long long off = (long long)(m0 + r) * lda + k0 + kk;
            As[kk * TM + r] = __bfloat162float(ah[off]) + __bfloat162float(al[off]);
        }
        for (int t = tid; t < TN * 16; t += 256) {
            int r = t >> 4, kk = t & 15;
            long long off = (long long)(n0 + r) * ldb + k0 + kk;
            Bs[kk * TN + r] = __bfloat162float(bh[off]) + __bfloat162float(bl[off]);
        }
        __syncthreads();
        for (int kk = 0; kk < 16; kk++)
            #pragma unroll
            for (int i = 0; i < RM; i++)
                #pragma unroll
                for (int j = 0; j < RN; j++)
                    acc[i][j] += As[kk * TM + ty * RM + i] * Bs[kk * TN + tx * RN + j];
    }
    #pragma unroll
    for (int i = 0; i < RM; i++) {
        int row = m0 + ty * RM + i;
        #pragma unroll
        for (int j = 0; j < RN; j++) {
            int col = n0 + tx * RN + j;
            long long rb = (long long)row * ldc + col + coff;
            float v = acc[i][j];
            if (BIAS) v += bias[col];
            if (RELU) v = fmaxf(v, 0.f);
            if (ACC)  v += C[rb];
            if (WRITEC) C[rb] = v;
            if (OSPLIT) split2(v, Oh + rb, Ol + rb);
        }
    }
#endif
}

template<int TN, int NS, bool BIAS, bool RELU, bool ACC, bool OSPLIT, bool WRITEC>
static void TG(const bf* Ah, const bf* Al, const bf* Bh, const bf* Bl,
               const float* bias, float* C, bf* Oh, bf* Ol,
               int M, int N, int Kd, int lda, int ldb, int ldc,
               int batch = 1, int Hb = 1,
               long long sA1 = 0, long long sA2 = 0,
               long long sB1 = 0, long long sB2 = 0,
               long long sC1 = 0, long long sC2 = 0)
{
    auto kern = tg_k<TN, NS, BIAS, RELU, ACC, OSPLIT, WRITEC>;
    int smem = 2048 + NS * ((2 * TM + 2 * TN) * 128);
    cudaFuncSetAttribute(kern, cudaFuncAttributeMaxDynamicSharedMemorySize, smem);
    dim3 g(N / TN, M / TM, batch);
    kern<<<g, 256, smem>>>(Ah, Al, Bh, Bl, bias, C, Oh, Ol, Kd, lda, ldb, ldc,
                           sA1, sA2, sB1, sB2, sC1, sC2, Hb);
}

// ---------------- transpose + split: in[R,C] fp32 -> out[C,R] bf16 hi/lo ----------------
__global__ void tsplit_k(const float* __restrict__ in, bf* __restrict__ oh, bf* __restrict__ ol,
                         int R, int C, long long inStride, long long outStride)
{
    __shared__ float t[32][33];
    in += blockIdx.z * inStride;
    oh += blockIdx.z * outStride;
    ol += blockIdx.z * outStride;
    int bx = blockIdx.x * 32, by = blockIdx.y * 32;
    int x = bx + threadIdx.x;
    #pragma unroll
    for (int j = threadIdx.y; j < 32; j += 8)
        t[j][threadIdx.x] = in[(long long)(by + j) * C + x];
    __syncthreads();
    int ox = by + threadIdx.x;
    #pragma unroll
    for (int j = threadIdx.y; j < 32; j += 8) {
        long long o = (long long)(bx + j) * R + ox;
        split2(t[threadIdx.x][j], oh + o, ol + o);
    }
}

// ---------------- split only ----------------
__global__ void split_k(const float* __restrict__ in, bf* __restrict__ oh,
                        bf* __restrict__ ol, long long n)
{
    long long i = (long long)blockIdx.x * 256 + threadIdx.x;
    if (i < n) split2(in[i], oh + i, ol + i);
}

// ---------------- embedding lookup * sqrt(D) (tokens int32) ----------------
__global__ void embed_k(const float* __restrict__ emb, const int* __restrict__ tok,
                        float* __restrict__ o)
{
    int t = blockIdx.x;
    int tk = tok[t];
    tk = (tk < 0) ? 0 : ((tk >= Vv) ? Vv - 1 : tk);
    const float* r = emb + (long long)tk * Dm;
    float* ow = o + (long long)t * Dm;
    for (int d = threadIdx.x; d < Dm; d += 256)
        ow[d] = r[d] * 22.62741699796952f;
}

// ---------------- layernorm -> split bf16 ----------------
__global__ void __launch_bounds__(128) ln_k(const float* __restrict__ x,
                                            const float* __restrict__ g,
                                            const float* __restrict__ b,
                                            bf* __restrict__ oh, bf* __restrict__ ol)
{
    long long t = blockIdx.x;
    const float* xr = x + t * Dm;
    int tid = threadIdx.x;
    float v0 = xr[tid], v1 = xr[tid + 128], v2 = xr[tid + 256], v3 = xr[tid + 384];
    __shared__ float r1[4], r2[4];
    float s = v0 + v1 + v2 + v3;
    #pragma unroll
    for (int m = 16; m; m >>= 1) s += __shfl_xor_sync(0xffffffffu, s, m);
    if ((tid & 31) == 0) r1[tid >> 5] = s;
    __syncthreads();
    float mean = (r1[0] + r1[1] + r1[2] + r1[3]) * (1.f / Dm);
    float d0 = v0 - mean, d1 = v1 - mean, d2 = v2 - mean, d3 = v3 - mean;
    float q = d0 * d0 + d1 * d1 + d2 * d2 + d3 * d3;
    #pragma unroll
    for (int m = 16; m; m >>= 1) q += __shfl_xor_sync(0xffffffffu, q, m);
    if ((tid & 31) == 0) r2[tid >> 5] = q;
    __syncthreads();
    float inv = rsqrtf((r2[0] + r2[1] + r2[2] + r2[3]) * (1.f / Dm) + 1e-5f);
    long long base = t * Dm;
    split2(d0 * inv * g[tid]       + b[tid],       oh + base + tid,       ol + base + tid);
    split2(d1 * inv * g[tid + 128] + b[tid + 128], oh + base + tid + 128, ol + base + tid + 128);
    split2(d2 * inv * g[tid + 256] + b[tid + 256], oh + base + tid + 256, ol + base + tid + 256);
    split2(d3 * inv * g[tid + 384] + b[tid + 384], oh + base + tid + 384, ol + base + tid + 384);
}

// ---------------- RoPE + split on Q,K ----------------
__global__ void rope_split_k(const float* __restrict__ q, const float* __restrict__ k,
                             bf* __restrict__ qh, bf* __restrict__ ql,
                             bf* __restrict__ kh, bf* __restrict__ kl)
{
    int idx = blockIdx.x * 256 + threadIdx.x;   // NT*H*32
    int d = idx & 31, h = (idx >> 5) & 7, t = idx >> 8;
    int pos = t & (Ss - 1);
    float ang = (float)pos * powf(10000.0f, -(float)d * (1.0f / 32.0f));
    float sn, cs;
    sincosf(ang, &sn, &cs);
    long long base = (long long)t * Dm + h * DKk + d;
    float q1 = q[base], q2 = q[base + 32];
    split2(q1 * cs - q2 * sn, qh + base, ql + base);
    split2(q2 * cs + q1 * sn, qh + base + 32, ql + base + 32);
    float k1 = k[base], k2 = k[base + 32];
    split2(k1 * cs - k2 * sn, kh + base, kl + base);
    split2(k2 * cs + k1 * sn, kh + base + 32, kl + base + 32);
}

// ---------------- masked softmax -> split bf16 probs ----------------
__global__ void __launch_bounds__(256) softmax_k(const float* __restrict__ sc,
                                                 bf* __restrict__ ph, bf* __restrict__ pl,
                                                 const int* __restrict__ keytok, int causal)
{
    long long row = blockIdx.x;
    int qi = (int)(row & (Ss - 1));
    int b  = (int)(row >> 13);
    const float* sr = sc + row * Ss;
    const int* kt = keytok + (long long)b * Ss;
    int tid = threadIdx.x;
    float v[4];
    float mx = -1e30f;
    #pragma unroll
    for (int i = 0; i < 4; i++) {
        int k = tid + i * 256;
        bool ok = (kt[k] != 0) && (!causal || k <= qi);
        float s = ok ? sr[k] * 0.125f : -1e30f;
        v[i] = s; mx = fmaxf(mx, s);
    }
    __shared__ float red[8];
    #pragma unroll
    for (int m = 16; m; m >>= 1) mx = fmaxf(mx, __shfl_xor_sync(0xffffffffu, mx, m));
    if ((tid & 31) == 0) red[tid >> 5] = mx;
    __syncthreads();
    mx = red[0];
    #pragma unroll
    for (int i = 1; i < 8; i++) mx = fmaxf(mx, red[i]);
    float sum = 0.f;
    #pragma unroll
    for (int i = 0; i < 4; i++) {
        float e = (v[i] > -1e29f) ? expf(v[i] - mx) : 0.f;
        v[i] = e; sum += e;
    }
    __syncthreads();
    #pragma unroll
    for (int m = 16; m; m >>= 1) sum += __shfl_xor_sync(0xffffffffu, sum, m);
    if ((tid & 31) == 0) red[tid >> 5] = sum;
    __syncthreads();
    sum = red[0] + red[1] + red[2] + red[3] + red[4] + red[5] + red[6] + red[7];
    float inv = 1.f / sum;
    long long base = row * Ss;
    #pragma unroll
    for (int i = 0; i < 4; i++)
        split2(v[i] * inv, ph + base + tid + i * 256, pl + base + tid + i * 256);
}

// ---------------- driver ----------------
extern "C" void kernel_launch(void* const* d_in, const int* in_sizes, int n_in,
                              void* d_out, int out_size)
{
    (void)in_sizes; (void)n_in; (void)out_size;
    const float* embed       = (const float*)d_in[0];
    const float* enc_attn_w  = (const float*)d_in[1];
    const float* enc_ffn_w1  = (const float*)d_in[2];
    const float* enc_ffn_b1  = (const float*)d_in[3];
    const float* enc_ffn_w2  = (const float*)d_in[4];
    const float* enc_ffn_b2  = (const float*)d_in[5];
    const float* enc_ln_g    = (const float*)d_in[6];
    const float* enc_ln_b    = (const float*)d_in[7];
    const float* enc_fg      = (const float*)d_in[8];
    const float* enc_fb      = (const float*)d_in[9];
    const float* dec_self_w  = (const float*)d_in[10];
    const float* dec_cross_w = (const float*)d_in[11];
    const float* dec_ffn_w1  = (const float*)d_in[12];
    const float* dec_ffn_b1  = (const float*)d_in[13];
    const float* dec_ffn_w2  = (const float*)d_in[14];
    const float* dec_ffn_b2  = (const float*)d_in[15];
    const float* dec_ln_g    = (const float*)d_in[16];
    const float* dec_ln_b    = (const float*)d_in[17];
    const float* dec_fg      = (const float*)d_in[18];
    const float* dec_fb      = (const float*)d_in[19];
    const int*   src         = (const int*)d_in[20];
    const int*   tgt         = (const int*)d_in[21];
    float* out = (float*)d_out;

    bf* BF = nullptr;  float* F = nullptr;
    cudaGetSymbolAddress((void**)&BF, g_bf);
    cudaGetSymbolAddress((void**)&F, g_f);
    float* X  = F + Xo;  float* Y  = F + Yo;
    float* Qf = F + Qo;  float* Kf = F + Ko;  float* Vf = F + Vo;
    float* SC = F + SCo;

    // ---- weight prep: transpose [in,out]->[out,in] + split bf16 hi/lo ----
    dim3 tb(32, 8);
    tsplit_k<<<dim3(16, 16, 24), tb>>>(enc_attn_w,  BF + WEAH, BF + WEAL, 512, 512, 262144LL, 262144LL);
    tsplit_k<<<dim3(16, 16, 24), tb>>>(dec_self_w,  BF + WDSH, BF + WDSL, 512, 512, 262144LL, 262144LL);
    tsplit_k<<<dim3(16, 16, 24), tb>>>(dec_cross_w, BF + WDCH, BF + WDCL, 512, 512, 262144LL, 262144LL);
    tsplit_k<<<dim3(64, 16, 6),  tb>>>(enc_ffn_w1,  BF + WE1H, BF + WE1L, 512, 2048, 1048576LL, 1048576LL);
    tsplit_k<<<dim3(16, 64, 6),  tb>>>(enc_ffn_w2,  BF + WE2H, BF + WE2L, 2048, 512, 1048576LL, 1048576LL);
    tsplit_k<<<dim3(64, 16, 6),  tb>>>(dec_ffn_w1,  BF + WD1H, BF + WD1L, 512, 2048, 1048576LL, 1048576LL);
    tsplit_k<<<dim3(16, 64, 6),  tb>>>(dec_ffn_w2,  BF + WD2H, BF + WD2L, 2048, 512, 1048576LL, 1048576LL);
    split_k<<<64000, 256>>>(embed, BF + EMBH, BF + EMBL, 16384000LL);

    const long long SD = 524288;    // S*Dm
    const long long SS2 = 1048576;  // S*S
    const long long HSS = 8388608;  // H*S*S

    auto attn = [&](const bf* aH, const bf* aL, const bf* kvH, const bf* kvL,
                    const bf* Wh, const bf* Wl, float* dst, const int* ktok,
                    bool rope, bool causal)
    {
        if (aH == kvH) {
            TG<64,3,0,0,0,0,1>(aH, aL, Wh, Wl, nullptr, Qf, nullptr, nullptr,
                               NT, Dm, Dm, Dm, Dm, Dm, 3, 3,
                               0, 0, 0, 262144LL, 0, 1048576LL);
        } else {
            TG<64,3,0,0,0,0,1>(aH, aL, Wh, Wl, nullptr, Qf, nullptr, nullptr,
                               NT, Dm, Dm, Dm, Dm, Dm);
            TG<64,3,0,0,0,0,1>(kvH, kvL, Wh + 262144, Wl + 262144, nullptr, Kf, nullptr, nullptr,
                               NT, Dm, Dm, Dm, Dm, Dm, 2, 2,
                               0, 0, 0, 262144LL, 0, 1048576LL);
        }
        if (rope) {
            rope_split_k<<<2048, 256>>>(Qf, Kf, BF + QBH, BF + QBL, BF + KBH, BF + KBL);
        } else {
            split_k<<<4096, 256>>>(Qf, BF + QBH, BF + QBL, 1048576LL);
            split_k<<<4096, 256>>>(Kf, BF + KBH, BF + KBL, 1048576LL);
        }
        tsplit_k<<<dim3(16, 32, 2), tb>>>(Vf, BF + VTH, BF + VTL, 1024, 512, 524288LL, 524288LL);
        // scores[b,h] = Q K^T
        TG<128,1,0,0,0,0,1>(BF + QBH, BF + QBL, BF + KBH, BF + KBL, nullptr, SC, nullptr, nullptr,
                            Ss, Ss, DKk, Dm, Dm, Ss, 16, 8,
                            SD, 64, SD, 64, HSS, SS2);
        softmax_k<<<16384, 256>>>(SC, BF + PRH, BF + PRL, ktok, causal ? 1 : 0);
        // ctx[b,h] = P @ V
        TG<64,3,0,0,0,1,0>(BF + PRH, BF + PRL, BF + VTH, BF + VTL, nullptr, nullptr,
                           BF + CTH, BF + CTL,
                           Ss, DKk, Ss, Ss, Ss, Dm, 16, 8,
                           HSS, SS2, SD, 65536LL, SD, 64);
        // dst += ctx @ Wo
        TG<64,3,0,0,1,0,1>(BF + CTH, BF + CTL, Wh + 3 * 262144, Wl + 3 * 262144, nullptr, dst,
                           nullptr, nullptr, NT, Dm, Dm, Dm, Dm, Dm);
    };

    auto ffn = [&](const bf* w1h, const bf* w1l, const float* b1,
                   const bf* w2h, const bf* w2l, const float* b2, float* dst)
    {
        TG<64,3,1,1,0,1,0>(BF + NBH, BF + NBL, w1h, w1l, b1, nullptr, BF + FNH, BF + FNL,
                           NT, Ff, Dm, Dm, Dm, Ff);
        TG<64,3,1,0,1,0,1>(BF + FNH, BF + FNL, w2h, w2l, b2, dst, nullptr, nullptr,
                           NT, Dm, Ff, Ff, Ff, Dm);
    };

    // ---- encoder ----
    embed_k<<<NT, 256>>>(embed, src, X);
    for (int i = 0; i < Ll; i++) {
        long long wo = (long long)i * 4 * 262144;
        ln_k<<<NT, 128>>>(X, enc_ln_g + i * 2 * Dm, enc_ln_b + i * 2 * Dm, BF + NBH, BF + NBL);
        attn(BF + NBH, BF + NBL, BF + NBH, BF + NBL, BF + WEAH + wo, BF + WEAL + wo,
             X, src, true, false);
        ln_k<<<NT, 128>>>(X, enc_ln_g + i * 2 * Dm + Dm, enc_ln_b + i * 2 * Dm + Dm, BF + NBH, BF + NBL);
        ffn(BF + WE1H + (long long)i * 1048576, BF + WE1L + (long long)i * 1048576, enc_ffn_b1 + i * Ff,
            BF + WE2H + (long long)i * 1048576, BF + WE2L + (long long)i * 1048576, enc_ffn_b2 + i * Dm, X);
    }
    ln_k<<<NT, 128>>>(X, enc_fg, enc_fb, BF + ENH, BF + ENL);

    // ---- decoder ----
    embed_k<<<NT, 256>>>(embed, tgt, Y);
    for (int i = 0; i < Ll; i++) {
        long long wo = (long long)i * 4 * 262144;
        ln_k<<<NT, 128>>>(Y, dec_ln_g + i * 3 * Dm, dec_ln_b + i * 3 * Dm, BF + NBH, BF + NBL);
        attn(BF + NBH, BF + NBL, BF + NBH, BF + NBL, BF + WDSH + wo, BF + WDSL + wo,
             Y, tgt, true, true);
        ln_k<<<NT, 128>>>(Y, dec_ln_g + i * 3 * Dm + Dm, dec_ln_b + i * 3 * Dm + Dm, BF + NBH, BF + NBL);
        attn(BF + NBH, BF + NBL, BF + ENH, BF + ENL, BF + WDCH + wo, BF + WDCL + wo,
             Y, src, false, false);
        ln_k<<<NT, 128>>>(Y, dec_ln_g + i * 3 * Dm + 2 * Dm, dec_ln_b + i * 3 * Dm + 2 * Dm, BF + NBH, BF + NBL);
        ffn(BF + WD1H + (long long)i * 1048576, BF + WD1L + (long long)i * 1048576, dec_ffn_b1 + i * Ff,
            BF + WD2H + (long long)i * 1048576, BF + WD2L + (long long)i * 1048576, dec_ffn_b2 + i * Dm, Y);
    }
    ln_k<<<NT, 128>>>(Y, dec_fg, dec_fb, BF + NBH, BF + NBL);

    // ---- tied output projection: out = y_norm @ embed^T ----
    TG<128,3,0,0,0,0,1>(BF + NBH, BF + NBL, BF + EMBH, BF + EMBL, nullptr, out, nullptr, nullptr,
                        NT, Vv, Dm, Dm, Dm, Vv);
}

// round 11
// speedup vs baseline: 1.5599x; 1.5599x over previous
#include <cuda_runtime.h>
#include <cuda_bf16.h>
#include <stdint.h>
#include <math.h>

#define Dm   512
#define Hh   8
#define DKk  64
#define Ff   2048
#define Ll   6
#define Bb   2
#define Ss   1024
#define NT   2048
#define Vv   32000
#define TM   128
typedef __nv_bfloat16 bf;

#if defined(__CUDA_ARCH__) && defined(__CUDA_ARCH_FEAT_SM103_ALL)
#define TC 1
#else
#define TC 0
#endif

// ---------------- bf16 pool offsets (elements) ----------------
#define WEAH 0LL
#define WEAL 6291456LL
#define WDSH 12582912LL
#define WDSL 18874368LL
#define WDCH 25165824LL
#define WDCL 31457280LL
#define WE1H 37748736LL
#define WE1L 44040192LL
#define WE2H 50331648LL
#define WE2L 56623104LL
#define WD1H 62914560LL
#define WD1L 69206016LL
#define WD2H 75497472LL
#define WD2L 81788928LL
#define EMBH 88080384LL
#define EMBL 104464384LL
#define NBH  120848384LL
#define NBL  121896960LL
#define ENH  122945536LL
#define ENL  123994112LL
#define FNH  125042688LL
#define FNL  129236992LL
#define QBH  133431296LL
#define QBL  134479872LL
#define KBH  135528448LL
#define KBL  136577024LL
#define CTH  137625600LL
#define CTL  138674176LL
#define VTH  139722752LL
#define VTL  140771328LL
#define PRH  141819904LL
#define PRL  158597120LL
#define BFTOT 175374336LL
// fp32 pool offsets
#define Xo   0LL
#define Yo   1048576LL
#define Qo   2097152LL
#define Ko   3145728LL
#define Vo   4194304LL
#define SCo  5242880LL
#define FTOT 22020096LL

__device__ __align__(256) bf    g_bf[BFTOT];
__device__ __align__(256) float g_f[FTOT];

// ---------------- helpers ----------------
__device__ __forceinline__ uint32_t smem_u32(const void* p) {
    uint32_t a;
    asm("{ .reg .u64 t; cvta.to.shared.u64 t, %1; cvt.u32.u64 %0, t; }" : "=r"(a) : "l"(p));
    return a;
}
__device__ __forceinline__ void split2(float v, bf* ph, bf* pl) {
    bf h = __float2bfloat16(v);
    *ph = h;
    *pl = __float2bfloat16(v - __bfloat162float(h));
}

#if TC
__device__ __forceinline__ uint32_t elect1() {
    uint32_t p;
    asm volatile("{ .reg .pred p; elect.sync _|p, 0xFFFFFFFF; selp.b32 %0,1,0,p; }" : "=r"(p));
    return p;
}
__device__ __forceinline__ uint64_t mk_desc(uint32_t a) {
    // SW128 K-major: layout=2, version=1, SBO=64, LBO=1
    return (uint64_t(2) << 61) | (uint64_t(1) << 46) | (uint64_t(64) << 32)
         | (uint64_t(1) << 16) | (uint64_t)((a >> 4) & 0x3FFF);
}
__device__ __forceinline__ void cpa16(uint32_t d, const void* s) {
    asm volatile("cp.async.cg.shared.global [%0], [%1], 16;" :: "r"(d), "l"(s));
}
__device__ __forceinline__ void cpa_commit() { asm volatile("cp.async.commit_group;" ::: "memory"); }
template<int N> __device__ __forceinline__ void cpa_wait() {
    asm volatile("cp.async.wait_group %0;" :: "n"(N) : "memory");
}
__device__ __forceinline__ void mma_f16_ss(uint32_t d, uint64_t da, uint64_t db,
                                           uint32_t idesc, uint32_t en) {
    asm volatile(
        "{\n\t.reg .pred p;\n\tsetp.ne.u32 p, %5, 0;\n\t"
        "tcgen05.mma.cta_group::1.kind::f16 [%0], %1, %2, %3, {%4, %4, %4, %4}, p;\n\t}"
        :: "r"(d), "l"(da), "l"(db), "r"(idesc), "r"(0u), "r"(en) : "memory");
}
#define TG_ALLOC(sm, n)   asm volatile("tcgen05.alloc.cta_group::1.sync.aligned.shared::cta.b32 [%0], %1;" :: "r"(sm), "r"(n) : "memory")
#define TG_DEALLOC(t, n)  asm volatile("tcgen05.dealloc.cta_group::1.sync.aligned.b32 %0, %1;" :: "r"(t), "r"(n))
#define TG_COMMIT(mb)     asm volatile("tcgen05.commit.cta_group::1.mbarrier::arrive::one.shared::cluster.b64 [%0];" :: "r"(mb) : "memory")
#define TG_FENCE_AFTER()  asm volatile("tcgen05.fence::after_thread_sync;" ::: "memory")
#define TG_WAIT_LD()      asm volatile("tcgen05.wait::ld.sync.aligned;" ::: "memory")
#define FENCE_PROXY()     asm volatile("fence.proxy.async.shared::cta;" ::: "memory")
#define MBAR_INIT(mb, c)  asm volatile("mbarrier.init.shared.b64 [%0], %1;" :: "r"(mb), "r"(c) : "memory")

__device__ __forceinline__ void mbar_wait(uint32_t mb, uint32_t parity) {
    asm volatile(
        "{\n\t.reg .pred P1;\n\t"
        "WL_%=:\n\t"
        "mbarrier.try_wait.parity.acquire.cta.shared::cta.b64 P1, [%0], %1, 0x989680;\n\t"
        "@P1 bra.uni WD_%=;\n\t"
        "bra.uni WL_%=;\n\t"
        "WD_%=:\n\t}"
        :: "r"(mb), "r"(parity) : "memory");
}
#define LDTM_X32(r, a) \
    asm volatile("tcgen05.ld.sync.aligned.32x32b.x32.b32 " \
        "{%0,%1,%2,%3,%4,%5,%6,%7,%8,%9,%10,%11,%12,%13,%14,%15," \
        "%16,%17,%18,%19,%20,%21,%22,%23,%24,%25,%26,%27,%28,%29,%30,%31}, [%32];" \
        : "=r"((r)[0]),"=r"((r)[1]),"=r"((r)[2]),"=r"((r)[3]),"=r"((r)[4]),"=r"((r)[5]),"=r"((r)[6]),"=r"((r)[7]), \
          "=r"((r)[8]),"=r"((r)[9]),"=r"((r)[10]),"=r"((r)[11]),"=r"((r)[12]),"=r"((r)[13]),"=r"((r)[14]),"=r"((r)[15]), \
          "=r"((r)[16]),"=r"((r)[17]),"=r"((r)[18]),"=r"((r)[19]),"=r"((r)[20]),"=r"((r)[21]),"=r"((r)[22]),"=r"((r)[23]), \
          "=r"((r)[24]),"=r"((r)[25]),"=r"((r)[26]),"=r"((r)[27]),"=r"((r)[28]),"=r"((r)[29]),"=r"((r)[30]),"=r"((r)[31]) \
        : "r"(a))
#endif  // TC

// ---------------- split-bf16 GEMM ----------------
// D[M,N] = (Ah+Al)[M,K] @ (Bh+Bl)[N,K]^T, fp32 accumulation.
// tcgen05 path on sm_103a; fp32-FMA fallback body on generic targets (correct, slow).
template<int TN, int NS, bool BIAS, bool RELU, bool ACC, bool OSPLIT, bool WRITEC>
__global__ void __launch_bounds__(256, 1) tg_k(
    const bf* __restrict__ Ah, const bf* __restrict__ Al,
    const bf* __restrict__ Bh, const bf* __restrict__ Bl,
    const float* __restrict__ bias, float* __restrict__ C,
    bf* __restrict__ Oh, bf* __restrict__ Ol,
    int Kd, int lda, int ldb, int ldc,
    long long sA1, long long sA2, long long sB1, long long sB2,
    long long sC1, long long sC2, int Hb)
{
    extern __shared__ char smraw[];
    int z = blockIdx.z, zb = z / Hb, zh = z - zb * Hb;
    const bf* ah = Ah + zb * sA1 + zh * sA2;
    const bf* al = Al + zb * sA1 + zh * sA2;
    const bf* bh = Bh + zb * sB1 + zh * sB2;
    const bf* bl = Bl + zb * sB1 + zh * sB2;
    const long long coff = zb * sC1 + zh * sC2;
    int m0 = blockIdx.y * TM, n0 = blockIdx.x * TN;
    int tid = threadIdx.x;

#if TC
    constexpr int SSZ = (2 * TM + 2 * TN) * 128;
    uint32_t smb = (smem_u32(smraw) + 1023u) & ~1023u;

    if (tid < NS) MBAR_INIT(smb + tid * 8, 1);
    if (tid < 32) TG_ALLOC(smb + 64, 128);
    __syncthreads();
    uint32_t tmem;
    asm("ld.shared.b32 %0,[%1];" : "=r"(tmem) : "r"(smb + 64));

    const uint32_t idesc = (1u << 4) | (1u << 7) | (1u << 10)
                         | ((uint32_t)(TN / 8) << 17) | ((uint32_t)(TM / 16) << 24);
    const int nk = Kd >> 6;

    auto fill = [&](int s, int kc) {
        uint32_t st = smb + 1024 + s * SSZ;
        int k0 = kc * 64;
        #pragma unroll
        for (int t = tid; t < TM * 8; t += 256) {
            int r = t >> 3, c = t & 7;
            uint32_t d = st + r * 128 + (uint32_t)((c * 16) ^ ((r & 7) << 4));
            long long off = (long long)(m0 + r) * lda + k0 + c * 8;
            cpa16(d, ah + off);
            cpa16(d + TM * 128, al + off);
        }
        #pragma unroll
        for (int t = tid; t < TN * 8; t += 256) {
            int r = t >> 3, c = t & 7;
            uint32_t d = st + 2 * TM * 128 + r * 128 + (uint32_t)((c * 16) ^ ((r & 7) << 4));
            long long off = (long long)(n0 + r) * ldb + k0 + c * 8;
            cpa16(d, bh + off);
            cpa16(d + TN * 128, bl + off);
        }
        cpa_commit();
    };

    int pre = (NS < nk) ? NS : nk;
    for (int i = 0; i < pre; i++) fill(i, i);
    for (int i = pre; i < NS; i++) cpa_commit();

    for (int i = 0; i < nk; i++) {
        int s = i % NS;
        cpa_wait<NS - 1>();
        __syncthreads();
        FENCE_PROXY();
        if (tid < 32 && elect1()) {
            uint32_t st = smb + 1024 + s * SSZ;
            uint64_t dah = mk_desc(st);
            uint64_t dal = mk_desc(st + TM * 128);
            uint64_t dbh = mk_desc(st + 2 * TM * 128);
            uint64_t dbl = mk_desc(st + 2 * TM * 128 + TN * 128);
            uint32_t en = (i > 0) ? 1u : 0u;
            #pragma unroll
            for (int j = 0; j < 4; j++) {
                mma_f16_ss(tmem, dah + j * 2, dbh + j * 2, idesc, en); en = 1u;
                mma_f16_ss(tmem, dah + j * 2, dbl + j * 2, idesc, 1u);
                mma_f16_ss(tmem, dal + j * 2, dbh + j * 2, idesc, 1u);
            }
            TG_COMMIT(smb + s * 8);
        }
        int pf = i + NS;
        if (pf < nk) {
            mbar_wait(smb + s * 8, (uint32_t)((i / NS) & 1));
            fill(s, pf);
        } else {
            cpa_commit();
        }
    }

    int sl = (nk - 1) % NS;
    mbar_wait(smb + sl * 8, (uint32_t)(((nk - 1) / NS) & 1));
    TG_FENCE_AFTER();

    int w = tid >> 5, lid = tid & 31;
    int sub = w & 3, half = w >> 2;
    int row = m0 + sub * 32 + lid;
    #pragma unroll
    for (int c0 = half * (TN / 2); c0 < (half + 1) * (TN / 2); c0 += 32) {
        uint32_t r[32];
        LDTM_X32(r, tmem + c0);
        TG_WAIT_LD();
        long long rb = (long long)row * ldc + n0 + c0 + coff;
        #pragma unroll
        for (int c = 0; c < 32; c++) {
            float v = __uint_as_float(r[c]);
            if (BIAS) v += bias[n0 + c0 + c];
            if (RELU) v = fmaxf(v, 0.f);
            if (ACC)  v += C[rb + c];
            if (WRITEC) C[rb + c] = v;
            if (OSPLIT) split2(v, Oh + rb + c, Ol + rb + c);
        }
    }
    __syncthreads();
    if (tid < 32) TG_DEALLOC(tmem, 128);
#else
    // -------- generic fallback: smem-tiled fp32 FMA, correct on any target --------
    float* As = (float*)smraw;          // [16][TM]
    float* Bs = As + 16 * TM;           // [16][TN]
    int ty = tid >> 4, tx = tid & 15;
    constexpr int RM = TM / 16, RN = TN / 16;
    float acc[RM][RN] = {};
    for (int k0 = 0; k0 < Kd; k0 += 16) {
        __syncthreads();
        for (int t = tid; t < TM * 16; t += 256) {
            int r = t >> 4, kk = t & 15;
            long long off = (long long)(m0 + r) * lda + k0 + kk;
            As[kk * TM + r] = __bfloat162float(ah[off]) + __bfloat162float(al[off]);
        }
        for (int t = tid; t < TN * 16; t += 256) {
            int r = t >> 4, kk = t & 15;
            long long off = (long long)(n0 + r) * ldb + k0 + kk;
            Bs[kk * TN + r] = __bfloat162float(bh[off]) + __bfloat162float(bl[off]);
        }
        __syncthreads();
        for (int kk = 0; kk < 16; kk++)
            #pragma unroll
            for (int i = 0; i < RM; i++)
                #pragma unroll
                for (int j = 0; j < RN; j++)
                    acc[i][j] += As[kk * TM + ty * RM + i] * Bs[kk * TN + tx * RN + j];
    }
    #pragma unroll
    for (int i = 0; i < RM; i++) {
        int row = m0 + ty * RM + i;
        #pragma unroll
        for (int j = 0; j < RN; j++) {
            int col = n0 + tx * RN + j;
            long long rb = (long long)row * ldc + col + coff;
            float v = acc[i][j];
            if (BIAS) v += bias[col];
            if (RELU) v = fmaxf(v, 0.f);
            if (ACC)  v += C[rb];
            if (WRITEC) C[rb] = v;
            if (OSPLIT) split2(v, Oh + rb, Ol + rb);
        }
    }
#endif
}

template<int TN, int NS, bool BIAS, bool RELU, bool ACC, bool OSPLIT, bool WRITEC>
static void TG(const bf* Ah, const bf* Al, const bf* Bh, const bf* Bl,
               const float* bias, float* C, bf* Oh, bf* Ol,
               int M, int N, int Kd, int lda, int ldb, int ldc,
               int batch = 1, int Hb = 1,
               long long sA1 = 0, long long sA2 = 0,
               long long sB1 = 0, long long sB2 = 0,
               long long sC1 = 0, long long sC2 = 0)
{
    auto kern = tg_k<TN, NS, BIAS, RELU, ACC, OSPLIT, WRITEC>;
    int smem = 2048 + NS * ((2 * TM + 2 * TN) * 128);
    cudaFuncSetAttribute(kern, cudaFuncAttributeMaxDynamicSharedMemorySize, smem);
    dim3 g(N / TN, M / TM, batch);
    kern<<<g, 256, smem>>>(Ah, Al, Bh, Bl, bias, C, Oh, Ol, Kd, lda, ldb, ldc,
                           sA1, sA2, sB1, sB2, sC1, sC2, Hb);
}

// ---------------- transpose + split: in[R,C] fp32 -> out[C,R] bf16 hi/lo ----------------
__global__ void tsplit_k(const float* __restrict__ in, bf* __restrict__ oh, bf* __restrict__ ol,
                         int R, int C, long long inStride, long long outStride)
{
    __shared__ float t[32][33];
    in += blockIdx.z * inStride;
    oh += blockIdx.z * outStride;
    ol += blockIdx.z * outStride;
    int bx = blockIdx.x * 32, by = blockIdx.y * 32;
    int x = bx + threadIdx.x;
    #pragma unroll
    for (int j = threadIdx.y; j < 32; j += 8)
        t[j][threadIdx.x] = in[(long long)(by + j) * C + x];
    __syncthreads();
    int ox = by + threadIdx.x;
    #pragma unroll
    for (int j = threadIdx.y; j < 32; j += 8) {
        long long o = (long long)(bx + j) * R + ox;
        split2(t[threadIdx.x][j], oh + o, ol + o);
    }
}

// ---------------- split only ----------------
__global__ void split_k(const float* __restrict__ in, bf* __restrict__ oh,
                        bf* __restrict__ ol, long long n)
{
    long long i = (long long)blockIdx.x * 256 + threadIdx.x;
    if (i < n) split2(in[i], oh + i, ol + i);
}

// ---------------- embedding lookup * sqrt(D) (tokens int32) ----------------
__global__ void embed_k(const float* __restrict__ emb, const int* __restrict__ tok,
                        float* __restrict__ o)
{
    int t = blockIdx.x;
    int tk = tok[t];
    tk = (tk < 0) ? 0 : ((tk >= Vv) ? Vv - 1 : tk);
    const float* r = emb + (long long)tk * Dm;
    float* ow = o + (long long)t * Dm;
    for (int d = threadIdx.x; d < Dm; d += 256)
        ow[d] = r[d] * 22.62741699796952f;
}

// ---------------- layernorm -> split bf16 ----------------
__global__ void __launch_bounds__(128) ln_k(const float* __restrict__ x,
                                            const float* __restrict__ g,
                                            const float* __restrict__ b,
                                            bf* __restrict__ oh, bf* __restrict__ ol)
{
    long long t = blockIdx.x;
    const float* xr = x + t * Dm;
    int tid = threadIdx.x;
    float v0 = xr[tid], v1 = xr[tid + 128], v2 = xr[tid + 256], v3 = xr[tid + 384];
    __shared__ float r1[4], r2[4];
    float s = v0 + v1 + v2 + v3;
    #pragma unroll
    for (int m = 16; m; m >>= 1) s += __shfl_xor_sync(0xffffffffu, s, m);
    if ((tid & 31) == 0) r1[tid >> 5] = s;
    __syncthreads();
    float mean = (r1[0] + r1[1] + r1[2] + r1[3]) * (1.f / Dm);
    float d0 = v0 - mean, d1 = v1 - mean, d2 = v2 - mean, d3 = v3 - mean;
    float q = d0 * d0 + d1 * d1 + d2 * d2 + d3 * d3;
    #pragma unroll
    for (int m = 16; m; m >>= 1) q += __shfl_xor_sync(0xffffffffu, q, m);
    if ((tid & 31) == 0) r2[tid >> 5] = q;
    __syncthreads();
    float inv = rsqrtf((r2[0] + r2[1] + r2[2] + r2[3]) * (1.f / Dm) + 1e-5f);
    long long base = t * Dm;
    split2(d0 * inv * g[tid]       + b[tid],       oh + base + tid,       ol + base + tid);
    split2(d1 * inv * g[tid + 128] + b[tid + 128], oh + base + tid + 128, ol + base + tid + 128);
    split2(d2 * inv * g[tid + 256] + b[tid + 256], oh + base + tid + 256, ol + base + tid + 256);
    split2(d3 * inv * g[tid + 384] + b[tid + 384], oh + base + tid + 384, ol + base + tid + 384);
}

// ---------------- RoPE + split on Q,K ----------------
__global__ void rope_split_k(const float* __restrict__ q, const float* __restrict__ k,
                             bf* __restrict__ qh, bf* __restrict__ ql,
                             bf* __restrict__ kh, bf* __restrict__ kl)
{
    int idx = blockIdx.x * 256 + threadIdx.x;   // NT*H*32
    int d = idx & 31, h = (idx >> 5) & 7, t = idx >> 8;
    int pos = t & (Ss - 1);
    float ang = (float)pos * powf(10000.0f, -(float)d * (1.0f / 32.0f));
    float sn, cs;
    sincosf(ang, &sn, &cs);
    long long base = (long long)t * Dm + h * DKk + d;
    float q1 = q[base], q2 = q[base + 32];
    split2(q1 * cs - q2 * sn, qh + base, ql + base);
    split2(q2 * cs + q1 * sn, qh + base + 32, ql + base + 32);
    float k1 = k[base], k2 = k[base + 32];
    split2(k1 * cs - k2 * sn, kh + base, kl + base);
    split2(k2 * cs + k1 * sn, kh + base + 32, kl + base + 32);
}

// ---------------- masked softmax -> split bf16 probs ----------------
__global__ void __launch_bounds__(256) softmax_k(const float* __restrict__ sc,
                                                 bf* __restrict__ ph, bf* __restrict__ pl,
                                                 const int* __restrict__ keytok, int causal)
{
    long long row = blockIdx.x;
    int qi = (int)(row & (Ss - 1));
    int b  = (int)(row >> 13);
    const float* sr = sc + row * Ss;
    const int* kt = keytok + (long long)b * Ss;
    int tid = threadIdx.x;
    float v[4];
    float mx = -1e30f;
    #pragma unroll
    for (int i = 0; i < 4; i++) {
        int k = tid + i * 256;
        bool ok = (kt[k] != 0) && (!causal || k <= qi);
        float s = ok ? sr[k] * 0.125f : -1e30f;
        v[i] = s; mx = fmaxf(mx, s);
    }
    __shared__ float red[8];
    #pragma unroll
    for (int m = 16; m; m >>= 1) mx = fmaxf(mx, __shfl_xor_sync(0xffffffffu, mx, m));
    if ((tid & 31) == 0) red[tid >> 5] = mx;
    __syncthreads();
    mx = red[0];
    #pragma unroll
    for (int i = 1; i < 8; i++) mx = fmaxf(mx, red[i]);
    float sum = 0.f;
    #pragma unroll
    for (int i = 0; i < 4; i++) {
        float e = (v[i] > -1e29f) ? expf(v[i] - mx) : 0.f;
        v[i] = e; sum += e;
    }
    __syncthreads();
    #pragma unroll
    for (int m = 16; m; m >>= 1) sum += __shfl_xor_sync(0xffffffffu, sum, m);
    if ((tid & 31) == 0) red[tid >> 5] = sum;
    __syncthreads();
    sum = red[0] + red[1] + red[2] + red[3] + red[4] + red[5] + red[6] + red[7];
    float inv = 1.f / sum;
    long long base = row * Ss;
    #pragma unroll
    for (int i = 0; i < 4; i++)
        split2(v[i] * inv, ph + base + tid + i * 256, pl + base + tid + i * 256);
}

// ---------------- driver ----------------
extern "C" void kernel_launch(void* const* d_in, const int* in_sizes, int n_in,
                              void* d_out, int out_size)
{
    (void)in_sizes; (void)n_in; (void)out_size;
    const float* embed       = (const float*)d_in[0];
    const float* enc_attn_w  = (const float*)d_in[1];
    const float* enc_ffn_w1  = (const float*)d_in[2];
    const float* enc_ffn_b1  = (const float*)d_in[3];
    const float* enc_ffn_w2  = (const float*)d_in[4];
    const float* enc_ffn_b2  = (const float*)d_in[5];
    const float* enc_ln_g    = (const float*)d_in[6];
    const float* enc_ln_b    = (const float*)d_in[7];
    const float* enc_fg      = (const float*)d_in[8];
    const float* enc_fb      = (const float*)d_in[9];
    const float* dec_self_w  = (const float*)d_in[10];
    const float* dec_cross_w = (const float*)d_in[11];
    const float* dec_ffn_w1  = (const float*)d_in[12];
    const float* dec_ffn_b1  = (const float*)d_in[13];
    const float* dec_ffn_w2  = (const float*)d_in[14];
    const float* dec_ffn_b2  = (const float*)d_in[15];
    const float* dec_ln_g    = (const float*)d_in[16];
    const float* dec_ln_b    = (const float*)d_in[17];
    const float* dec_fg      = (const float*)d_in[18];
    const float* dec_fb      = (const float*)d_in[19];
    const int*   src         = (const int*)d_in[20];
    const int*   tgt         = (const int*)d_in[21];
    float* out = (float*)d_out;

    bf* BF = nullptr;  float* F = nullptr;
    cudaGetSymbolAddress((void**)&BF, g_bf);
    cudaGetSymbolAddress((void**)&F, g_f);
    float* X  = F + Xo;  float* Y  = F + Yo;
    float* Qf = F + Qo;  float* Kf = F + Ko;  float* Vf = F + Vo;
    float* SC = F + SCo;

    // ---- weight prep: transpose [in,out]->[out,in] + split bf16 hi/lo ----
    dim3 tb(32, 8);
    tsplit_k<<<dim3(16, 16, 24), tb>>>(enc_attn_w,  BF + WEAH, BF + WEAL, 512, 512, 262144LL, 262144LL);
    tsplit_k<<<dim3(16, 16, 24), tb>>>(dec_self_w,  BF + WDSH, BF + WDSL, 512, 512, 262144LL, 262144LL);
    tsplit_k<<<dim3(16, 16, 24), tb>>>(dec_cross_w, BF + WDCH, BF + WDCL, 512, 512, 262144LL, 262144LL);
    tsplit_k<<<dim3(64, 16, 6),  tb>>>(enc_ffn_w1,  BF + WE1H, BF + WE1L, 512, 2048, 1048576LL, 1048576LL);
    tsplit_k<<<dim3(16, 64, 6),  tb>>>(enc_ffn_w2,  BF + WE2H, BF + WE2L, 2048, 512, 1048576LL, 1048576LL);
    tsplit_k<<<dim3(64, 16, 6),  tb>>>(dec_ffn_w1,  BF + WD1H, BF + WD1L, 512, 2048, 1048576LL, 1048576LL);
    tsplit_k<<<dim3(16, 64, 6),  tb>>>(dec_ffn_w2,  BF + WD2H, BF + WD2L, 2048, 512, 1048576LL, 1048576LL);
    split_k<<<64000, 256>>>(embed, BF + EMBH, BF + EMBL, 16384000LL);

    const long long SD = 524288;    // S*Dm
    const long long SS2 = 1048576;  // S*S
    const long long HSS = 8388608;  // H*S*S

    auto attn = [&](const bf* aH, const bf* aL, const bf* kvH, const bf* kvL,
                    const bf* Wh, const bf* Wl, float* dst, const int* ktok,
                    bool rope, bool causal)
    {
        if (aH == kvH) {
            TG<64,3,0,0,0,0,1>(aH, aL, Wh, Wl, nullptr, Qf, nullptr, nullptr,
                               NT, Dm, Dm, Dm, Dm, Dm, 3, 3,
                               0, 0, 0, 262144LL, 0, 1048576LL);
        } else {
            TG<64,3,0,0,0,0,1>(aH, aL, Wh, Wl, nullptr, Qf, nullptr, nullptr,
                               NT, Dm, Dm, Dm, Dm, Dm);
            TG<64,3,0,0,0,0,1>(kvH, kvL, Wh + 262144, Wl + 262144, nullptr, Kf, nullptr, nullptr,
                               NT, Dm, Dm, Dm, Dm, Dm, 2, 2,
                               0, 0, 0, 262144LL, 0, 1048576LL);
        }
        if (rope) {
            rope_split_k<<<2048, 256>>>(Qf, Kf, BF + QBH, BF + QBL, BF + KBH, BF + KBL);
        } else {
            split_k<<<4096, 256>>>(Qf, BF + QBH, BF + QBL, 1048576LL);
            split_k<<<4096, 256>>>(Kf, BF + KBH, BF + KBL, 1048576LL);
        }
        tsplit_k<<<dim3(16, 32, 2), tb>>>(Vf, BF + VTH, BF + VTL, 1024, 512, 524288LL, 524288LL);
        // scores[b,h] = Q K^T
        TG<128,1,0,0,0,0,1>(BF + QBH, BF + QBL, BF + KBH, BF + KBL, nullptr, SC, nullptr, nullptr,
                            Ss, Ss, DKk, Dm, Dm, Ss, 16, 8,
                            SD, 64, SD, 64, HSS, SS2);
        softmax_k<<<16384, 256>>>(SC, BF + PRH, BF + PRL, ktok, causal ? 1 : 0);
        // ctx[b,h] = P @ V
        TG<64,3,0,0,0,1,0>(BF + PRH, BF + PRL, BF + VTH, BF + VTL, nullptr, nullptr,
                           BF + CTH, BF + CTL,
                           Ss, DKk, Ss, Ss, Ss, Dm, 16, 8,
                           HSS, SS2, SD, 65536LL, SD, 64);
        // dst += ctx @ Wo
        TG<64,3,0,0,1,0,1>(BF + CTH, BF + CTL, Wh + 3 * 262144, Wl + 3 * 262144, nullptr, dst,
                           nullptr, nullptr, NT, Dm, Dm, Dm, Dm, Dm);
    };

    auto ffn = [&](const bf* w1h, const bf* w1l, const float* b1,
                   const bf* w2h, const bf* w2l, const float* b2, float* dst)
    {
        TG<64,3,1,1,0,1,0>(BF + NBH, BF + NBL, w1h, w1l, b1, nullptr, BF + FNH, BF + FNL,
                           NT, Ff, Dm, Dm, Dm, Ff);
        TG<64,3,1,0,1,0,1>(BF + FNH, BF + FNL, w2h, w2l, b2, dst, nullptr, nullptr,
                           NT, Dm, Ff, Ff, Ff, Dm);
    };

    // ---- encoder ----
    embed_k<<<NT, 256>>>(embed, src, X);
    for (int i = 0; i < Ll; i++) {
        long long wo = (long long)i * 4 * 262144;
        ln_k<<<NT, 128>>>(X, enc_ln_g + i * 2 * Dm, enc_ln_b + i * 2 * Dm, BF + NBH, BF + NBL);
        attn(BF + NBH, BF + NBL, BF + NBH, BF + NBL, BF + WEAH + wo, BF + WEAL + wo,
             X, src, true, false);
        ln_k<<<NT, 128>>>(X, enc_ln_g + i * 2 * Dm + Dm, enc_ln_b + i * 2 * Dm + Dm, BF + NBH, BF + NBL);
        ffn(BF + WE1H + (long long)i * 1048576, BF + WE1L + (long long)i * 1048576, enc_ffn_b1 + i * Ff,
            BF + WE2H + (long long)i * 1048576, BF + WE2L + (long long)i * 1048576, enc_ffn_b2 + i * Dm, X);
    }
    ln_k<<<NT, 128>>>(X, enc_fg, enc_fb, BF + ENH, BF + ENL);

    // ---- decoder ----
    embed_k<<<NT, 256>>>(embed, tgt, Y);
    for (int i = 0; i < Ll; i++) {
        long long wo = (long long)i * 4 * 262144;
        ln_k<<<NT, 128>>>(Y, dec_ln_g + i * 3 * Dm, dec_ln_b + i * 3 * Dm, BF + NBH, BF + NBL);
        attn(BF + NBH, BF + NBL, BF + NBH, BF + NBL, BF + WDSH + wo, BF + WDSL + wo,
             Y, tgt, true, true);
        ln_k<<<NT, 128>>>(Y, dec_ln_g + i * 3 * Dm + Dm, dec_ln_b + i * 3 * Dm + Dm, BF + NBH, BF + NBL);
        attn(BF + NBH, BF + NBL, BF + ENH, BF + ENL, BF + WDCH + wo, BF + WDCL + wo,
             Y, src, false, false);
        ln_k<<<NT, 128>>>(Y, dec_ln_g + i * 3 * Dm + 2 * Dm, dec_ln_b + i * 3 * Dm + 2 * Dm, BF + NBH, BF + NBL);
        ffn(BF + WD1H + (long long)i * 1048576, BF + WD1L + (long long)i * 1048576, dec_ffn_b1 + i * Ff,
            BF + WD2H + (long long)i * 1048576, BF + WD2L + (long long)i * 1048576, dec_ffn_b2 + i * Dm, Y);
    }
    ln_k<<<NT, 128>>>(Y, dec_fg, dec_fb, BF + NBH, BF + NBL);

    // ---- tied output projection: out = y_norm @ embed^T ----
    TG<128,3,0,0,0,0,1>(BF + NBH, BF + NBL, BF + EMBH, BF + EMBL, nullptr, out, nullptr, nullptr,
                        NT, Vv, Dm, Dm, Dm, Vv);
}